// round 8
// baseline (speedup 1.0000x reference)
#include <cuda_runtime.h>
#include <math.h>
#include <stdint.h>

#define BATCH 16
#define CCH   512
#define NPIX  4096
#define KSPLIT 4

// ---------------- scratch (__device__ globals; no allocation allowed) ----------------
__device__ float g_Gp  [(size_t)KSPLIT * BATCH * CCH * CCH];   // split-K partials
__device__ float g_G   [(size_t)BATCH * CCH * CCH];
__device__ float g_T1  [(size_t)BATCH * CCH * CCH];
__device__ float g_S   [(size_t)BATCH * CCH * CCH];
__device__ float g_attn[(size_t)BATCH * CCH * CCH];
__device__ float g_T2  [(size_t)BATCH * CCH * CCH];
__device__ float g_P   [(size_t)BATCH * CCH * CCH];
__device__ float g_ga  [BATCH * CCH];   // gamma * rstd
__device__ float g_be  [BATCH * CCH];   // beta - mean*ga
__device__ float g_sx  [BATCH * CCH];   // raw channel sums of x
__device__ float g_hs  [BATCH * CCH];   // ga*sx + N*be (row sums of hn)
__device__ float g_u   [BATCH * CCH];
__device__ float g_w   [BATCH * CCH];
__device__ float g_v1  [BATCH * CCH];
__device__ float g_t   [BATCH * CCH];
__device__ float g_r   [BATCH * CCH];

__device__ __forceinline__ float tf32r(float x) {
    float y; asm("cvt.rna.tf32.f32 %0, %1;" : "=f"(y) : "f"(x)); return y;
}

__device__ __forceinline__ void mma_tf32_16x8x8(float* d, const uint32_t* a, const uint32_t* b) {
    asm volatile(
        "mma.sync.aligned.m16n8k8.row.col.f32.tf32.tf32.f32 "
        "{%0,%1,%2,%3}, {%4,%5,%6,%7}, {%8,%9}, {%0,%1,%2,%3};"
        : "+f"(d[0]), "+f"(d[1]), "+f"(d[2]), "+f"(d[3])
        : "r"(a[0]), "r"(a[1]), "r"(a[2]), "r"(a[3]), "r"(b[0]), "r"(b[1]));
}

// ---------------- GroupNorm stats: emits ga/be/sx/hs ----------------
__global__ void gn_stats_kernel(const float* __restrict__ x,
                                const float* __restrict__ gamma,
                                const float* __restrict__ beta)
{
    int bg = blockIdx.x;
    int b = bg >> 5, g = bg & 31;
    size_t base = (size_t)bg * (16 * NPIX);
    int wid = threadIdx.x >> 5, lane = threadIdx.x & 31;
    __shared__ float chs[16], chss[16];
    __shared__ float2 st_sh;

#pragma unroll
    for (int c2 = 0; c2 < 2; c2++) {
        int cl = wid * 2 + c2;
        const float4* xp = (const float4*)(x + base + (size_t)cl * NPIX);
        float s = 0.f, ss = 0.f;
        for (int i = lane; i < NPIX / 4; i += 32) {
            float4 v = xp[i];
            s  += v.x + v.y + v.z + v.w;
            ss += v.x * v.x + v.y * v.y + v.z * v.z + v.w * v.w;
        }
#pragma unroll
        for (int o = 16; o > 0; o >>= 1) {
            s  += __shfl_xor_sync(0xffffffffu, s, o);
            ss += __shfl_xor_sync(0xffffffffu, ss, o);
        }
        if (lane == 0) { chs[cl] = s; chss[cl] = ss; }
    }
    __syncthreads();
    if (threadIdx.x == 0) {
        float s = 0.f, ss = 0.f;
#pragma unroll
        for (int i = 0; i < 16; i++) { s += chs[i]; ss += chss[i]; }
        float mean = s * (1.f / (16 * NPIX));
        float var  = ss * (1.f / (16 * NPIX)) - mean * mean;
        st_sh = make_float2(mean, rsqrtf(var + 1e-6f));
    }
    __syncthreads();
    if (threadIdx.x < 16) {
        int cl = threadIdx.x, ch = g * 16 + cl;
        float2 st = st_sh;
        float ga = gamma[ch] * st.y;
        float be = beta[ch] - st.x * ga;
        float sx = chs[cl];
        int idx = (b << 9) + ch;
        g_ga[idx] = ga;
        g_be[idx] = be;
        g_sx[idx] = sx;
        g_hs[idx] = ga * sx + (float)NPIX * be;
    }
}

// ---------------- tf32 mma.sync GEMM: D = scale*A*OP(B) (+bias)(+resid)(*cscale) ----------------
// CTA 256x128, BK=32, 8 warps (4x2), warp tile 64x64, m16n8k8.
// BNN=false: B read as [N,K] row-major (D = A*B^T).  BNN=true: B read as [K,N] row-major (D = A*B).
// SPLIT: 3x-tf32 hi/lo planes (NT path only).
#define A_SUB 132
#define B_SUB 66
#define A_FLOATS (64 * A_SUB)            // 8448
#define B_REGION 4352                    // max(NT 4224, BNN 32*136)
#define BNN_ROW 136                      // padded natural-layout row (conflict-free frag reads)
#define STAGE_F (A_FLOATS + B_REGION)    // 12800 floats
#define SMEM_PLAIN (2 * STAGE_F * 4)     // 102400 B
#define SMEM_SPLIT (4 * STAGE_F * 4)     // 204800 B

template<bool SPLIT, bool BNN>
__global__ void __launch_bounds__(256, 1) gemm_tc(
    const float* __restrict__ A, int lda, long long sA,
    const float* __restrict__ B, int ldb, long long sB,
    float* __restrict__ D, int ldd, long long sD,
    const float* __restrict__ bias, int bias_mode, long long sBias,
    const float* __restrict__ resid,
    const float* __restrict__ cscale,   // per-(batch,col) multiplier, stride CCH; nullable
    float scale, int K, int sym, long long sKsp)
{
    extern __shared__ float smem[];

    int tid = threadIdx.x, wid = tid >> 5, lane = tid & 31;
    int z = blockIdx.z;
    int row0, col0;
    if (sym) {
        int t = blockIdx.x;
        row0 = (t < 2) ? 0 : 256;
        col0 = ((t < 2) ? t : (t - 2)) << 7;
    } else {
        row0 = blockIdx.y << 8;
        col0 = blockIdx.x << 7;
    }

    A += (size_t)z * sA + (size_t)row0 * lda;
    B += (size_t)z * sB;
    D += (size_t)z * sD;
    if (sym) {
        A += (size_t)blockIdx.y * K;
        B += (size_t)blockIdx.y * K;     // NT only (sym never BNN)
        D += (size_t)blockIdx.y * sKsp;
    }
    if (resid) resid += (size_t)z * sD;

    const int r_  = tid >> 3;
    const int c0_ = (tid & 7) << 2;
    const int kt_ = c0_ >> 3;
    int offA[8], offB[4];
#pragma unroll
    for (int i = 0; i < 8; i++) {
        int r = r_ + (i << 5);
        int mt = r >> 4, rr = r & 15;
        int regA = (((c0_ & 7) >= 4) ? 2 : 0) + ((rr >> 3) & 1);
        offA[i] = (mt * 4 + kt_) * A_SUB + ((rr & 7) << 4) + regA;
    }
    if (!BNN) {
#pragma unroll
        for (int i = 0; i < 4; i++) {
            int r = r_ + (i << 5);
            int nt = r >> 3, nn = r & 7;
            int regB = ((c0_ & 7) >= 4) ? 1 : 0;
            offB[i] = A_FLOATS + (nt * 4 + kt_) * B_SUB + (nn << 3) + regB;
        }
    } else {
#pragma unroll
        for (int i = 0; i < 4; i++) {
            int k = (tid >> 5) + (i << 3);        // 0..31
            int n4 = (tid & 31) << 2;             // 0..124
            offB[i] = A_FLOATS + k * BNN_ROW + n4;
        }
    }

    const float* aG = A + (size_t)r_ * lda + c0_;
    const size_t aStep = (size_t)32 * lda;
    const float* bG;
    size_t bIstep, bSstep;
    if (BNN) {
        bG = B + col0 + (size_t)(tid >> 5) * ldb + ((size_t)(tid & 31) << 2);
        bIstep = (size_t)8 * ldb;
        bSstep = (size_t)32 * ldb;
    } else {
        bG = B + (size_t)(col0 + r_) * ldb + c0_;
        bIstep = (size_t)32 * ldb;
        bSstep = 32;
    }

    const int wm4 = (wid & 3) * 4;
    const int wn8 = (wid >> 2) * 8;

    float acc[4][8][4];
#pragma unroll
    for (int mt = 0; mt < 4; mt++)
#pragma unroll
        for (int nt = 0; nt < 8; nt++)
#pragma unroll
            for (int rgi = 0; rgi < 4; rgi++) acc[mt][nt][rgi] = 0.f;

    const int NK = K >> 5;
    float4 ra[8], rb[4];

    auto stage_load = [&](int s) {
        const float* aN = aG + (size_t)s * 32;
#pragma unroll
        for (int i = 0; i < 8; i++) ra[i] = *(const float4*)(aN + i * aStep);
        const float* bN = bG + (size_t)s * bSstep;
#pragma unroll
        for (int i = 0; i < 4; i++) rb[i] = *(const float4*)(bN + i * bIstep);
    };
    auto stage_store = [&](float* base) {
#pragma unroll
        for (int i = 0; i < 8; i++) {
            float* sa = base + offA[i];
            float h;
            h = tf32r(ra[i].x); sa[0]  = h; if (SPLIT) (base + STAGE_F + offA[i])[0]  = tf32r(ra[i].x - h);
            h = tf32r(ra[i].y); sa[4]  = h; if (SPLIT) (base + STAGE_F + offA[i])[4]  = tf32r(ra[i].y - h);
            h = tf32r(ra[i].z); sa[8]  = h; if (SPLIT) (base + STAGE_F + offA[i])[8]  = tf32r(ra[i].z - h);
            h = tf32r(ra[i].w); sa[12] = h; if (SPLIT) (base + STAGE_F + offA[i])[12] = tf32r(ra[i].w - h);
        }
        if (!BNN) {
#pragma unroll
            for (int i = 0; i < 4; i++) {
                float* sb = base + offB[i];
                float h;
                h = tf32r(rb[i].x); sb[0] = h; if (SPLIT) (base + STAGE_F + offB[i])[0] = tf32r(rb[i].x - h);
                h = tf32r(rb[i].y); sb[2] = h; if (SPLIT) (base + STAGE_F + offB[i])[2] = tf32r(rb[i].y - h);
                h = tf32r(rb[i].z); sb[4] = h; if (SPLIT) (base + STAGE_F + offB[i])[4] = tf32r(rb[i].z - h);
                h = tf32r(rb[i].w); sb[6] = h; if (SPLIT) (base + STAGE_F + offB[i])[6] = tf32r(rb[i].w - h);
            }
        } else {
#pragma unroll
            for (int i = 0; i < 4; i++) {
                float4 v;
                v.x = tf32r(rb[i].x); v.y = tf32r(rb[i].y);
                v.z = tf32r(rb[i].z); v.w = tf32r(rb[i].w);
                *(float4*)(base + offB[i]) = v;
            }
        }
    };

    stage_load(0);
    stage_store(smem);
    __syncthreads();

    for (int s = 0; s < NK; s++) {
        if (s + 1 < NK) stage_load(s + 1);
        const float* cS = smem + (s & 1) * (SPLIT ? 2 * STAGE_F : STAGE_F);
#pragma unroll
        for (int kt = 0; kt < 4; kt++) {
            uint4 af[4]; uint2 bf[8];
#pragma unroll
            for (int mt = 0; mt < 4; mt++)
                af[mt] = *(const uint4*)(cS + ((wm4 + mt) * 4 + kt) * A_SUB + (lane << 2));
            if (!BNN) {
#pragma unroll
                for (int nt = 0; nt < 8; nt++)
                    bf[nt] = *(const uint2*)(cS + A_FLOATS + ((wn8 + nt) * 4 + kt) * B_SUB + (lane << 1));
            } else {
                const uint32_t* cSu = (const uint32_t*)(cS + A_FLOATS);
                int kb = (kt << 3) + (lane & 3);
                int nb = (lane >> 2);
#pragma unroll
                for (int nt = 0; nt < 8; nt++) {
                    bf[nt].x = cSu[kb * BNN_ROW + ((wn8 + nt) << 3) + nb];
                    bf[nt].y = cSu[(kb + 4) * BNN_ROW + ((wn8 + nt) << 3) + nb];
                }
            }
#pragma unroll
            for (int mt = 0; mt < 4; mt++)
#pragma unroll
                for (int nt = 0; nt < 8; nt++)
                    mma_tf32_16x8x8(acc[mt][nt], &af[mt].x, &bf[nt].x);
            if (SPLIT) {
                uint4 al[4]; uint2 bl[8];
#pragma unroll
                for (int mt = 0; mt < 4; mt++)
                    al[mt] = *(const uint4*)(cS + STAGE_F + ((wm4 + mt) * 4 + kt) * A_SUB + (lane << 2));
#pragma unroll
                for (int nt = 0; nt < 8; nt++)
                    bl[nt] = *(const uint2*)(cS + STAGE_F + A_FLOATS + ((wn8 + nt) * 4 + kt) * B_SUB + (lane << 1));
#pragma unroll
                for (int mt = 0; mt < 4; mt++)
#pragma unroll
                    for (int nt = 0; nt < 8; nt++) {
                        mma_tf32_16x8x8(acc[mt][nt], &af[mt].x, &bl[nt].x);
                        mma_tf32_16x8x8(acc[mt][nt], &al[mt].x, &bf[nt].x);
                    }
            }
        }
        if (s + 1 < NK) {
            stage_store(smem + ((s + 1) & 1) * (SPLIT ? 2 * STAGE_F : STAGE_F));
            __syncthreads();
        }
    }

    const int lane4 = lane >> 2, laneq = lane & 3;
    const int wrow = row0 + (wid & 3) * 64;
    const int wcol = col0 + (wid >> 2) * 64;
#pragma unroll
    for (int mt = 0; mt < 4; mt++) {
#pragma unroll
        for (int half = 0; half < 2; half++) {
            int r = wrow + mt * 16 + lane4 + half * 8;
            float rb_ = (bias_mode == 1) ? bias[(size_t)z * sBias + r] : 0.f;
            float* drow = D + (size_t)r * ldd + wcol;
            const float* rrow = resid ? (resid + (size_t)r * ldd + wcol) : nullptr;
#pragma unroll
            for (int nt = 0; nt < 8; nt++) {
                int c = nt * 8 + laneq * 2;
                float2 o;
                o.x = acc[mt][nt][half * 2 + 0] * scale;
                o.y = acc[mt][nt][half * 2 + 1] * scale;
                if (cscale) {
                    o.x *= cscale[(size_t)z * CCH + wcol + c];
                    o.y *= cscale[(size_t)z * CCH + wcol + c + 1];
                }
                o.x += rb_; o.y += rb_;
                if (bias_mode == 2) {
                    o.x += bias[(size_t)z * sBias + wcol + c];
                    o.y += bias[(size_t)z * sBias + wcol + c + 1];
                }
                if (rrow) { o.x += rrow[c]; o.y += rrow[c + 1]; }
                *(float2*)(drow + c) = o;
            }
        }
    }
}

// ---------------- reduce split-K Gram partials + exact GN rank-1 corrections ----------------
__global__ void __launch_bounds__(256) reduce_g_kernel(const float* __restrict__ Gp,
                                                       float* __restrict__ G)
{
    const size_t per = (size_t)BATCH * CCH * CCH;
    int b = blockIdx.y;
    int idx = (blockIdx.x * 256 + threadIdx.x) << 2;
    int i = idx >> 9, j = idx & 511;
    if (i < 256 && j >= 256) return;
    size_t off = (size_t)b * CCH * CCH + idx;
    float4 s0 = *(const float4*)(Gp + off);
    float4 s1 = *(const float4*)(Gp + per + off);
    float4 s2 = *(const float4*)(Gp + 2 * per + off);
    float4 s3 = *(const float4*)(Gp + 3 * per + off);
    int ri = (b << 9) + i, rj = (b << 9) + j;
    float gai = g_ga[ri], hsxi = gai * g_sx[ri], bei = g_be[ri];
    float4 gaj = *(const float4*)(g_ga + rj);
    float4 bej = *(const float4*)(g_be + rj);
    float4 hsj = *(const float4*)(g_hs + rj);
    float4 o;
    o.x = gai * gaj.x * ((s0.x + s1.x) + (s2.x + s3.x)) + hsxi * bej.x + bei * hsj.x;
    o.y = gai * gaj.y * ((s0.y + s1.y) + (s2.y + s3.y)) + hsxi * bej.y + bei * hsj.y;
    o.z = gai * gaj.z * ((s0.z + s1.z) + (s2.z + s3.z)) + hsxi * bej.z + bei * hsj.z;
    o.w = gai * gaj.w * ((s0.w + s1.w) + (s2.w + s3.w)) + hsxi * bej.w + bei * hsj.w;
    *(float4*)(G + off) = o;
}

// ---------------- mirror upper-right block of symmetric G ----------------
__global__ void __launch_bounds__(256) mirror_kernel(float* __restrict__ G)
{
    __shared__ float t[32][33];
    float* Gb = G + (size_t)blockIdx.z * CCH * CCH;
    int i0 = blockIdx.y << 5, j0 = 256 + (blockIdx.x << 5);
    int lx = threadIdx.x & 31, ly = threadIdx.x >> 5;
#pragma unroll
    for (int ii = 0; ii < 4; ii++)
        t[ly + ii * 8][lx] = Gb[(size_t)(j0 + ly + ii * 8) * CCH + i0 + lx];
    __syncthreads();
#pragma unroll
    for (int ii = 0; ii < 4; ii++)
        Gb[(size_t)(i0 + ly + ii * 8) * CCH + j0 + lx] = t[lx][ly + ii * 8];
}

// ---------------- softmax with rank-1 bias corrections ----------------
__global__ void softmax_kernel(const float* __restrict__ S, float* __restrict__ attn,
                               const float* __restrict__ u, const float* __restrict__ w,
                               const float* __restrict__ bq, const float* __restrict__ bk,
                               float scale)
{
    int gw = (blockIdx.x * blockDim.x + threadIdx.x) >> 5;
    int lane = threadIdx.x & 31;
    if (gw >= BATCH * CCH) return;
    int b = gw >> 9, c = gw & 511;
    const float* row = S + (size_t)gw * CCH;
    float* orow = attn + (size_t)gw * CCH;
    float uc = u[(b << 9) + c], bqc = bq[c];
    float v[16];
    float m = -3.4e38f;
#pragma unroll
    for (int i = 0; i < 16; i++) {
        int d = lane + (i << 5);
        float bkd = bk[d], wd = w[(b << 9) + d];
        v[i] = scale * (row[d] + uc * bkd + bqc * wd + (float)NPIX * bqc * bkd);
        m = fmaxf(m, v[i]);
    }
#pragma unroll
    for (int o = 16; o > 0; o >>= 1) m = fmaxf(m, __shfl_xor_sync(0xffffffffu, m, o));
    float s = 0.f;
#pragma unroll
    for (int i = 0; i < 16; i++) { v[i] = __expf(v[i] - m); s += v[i]; }
#pragma unroll
    for (int o = 16; o > 0; o >>= 1) s += __shfl_xor_sync(0xffffffffu, s, o);
    float inv = 1.f / s;
#pragma unroll
    for (int i = 0; i < 16; i++) orow[lane + (i << 5)] = v[i] * inv;
}

// ---------------- batched matvec: y[b,m] = W_b[m,:].(v_b + v2) (+bias[m]) ----------------
__global__ void matvec_kernel(const float* __restrict__ W, long long sW,
                              const float* __restrict__ v, long long sV,
                              const float* __restrict__ v2,
                              float* __restrict__ y, long long sY,
                              const float* __restrict__ bias)
{
    int b = blockIdx.y;
    int m = (blockIdx.x << 3) + (threadIdx.x >> 5);
    int lane = threadIdx.x & 31;
    const float* wr = W + (size_t)b * sW + (size_t)m * CCH;
    const float* vv = v + (size_t)b * sV;
    float s = 0.f;
    for (int k = lane; k < CCH; k += 32) {
        float vk = vv[k];
        if (v2) vk += v2[k];
        s += wr[k] * vk;
    }
#pragma unroll
    for (int o = 16; o > 0; o >>= 1) s += __shfl_xor_sync(0xffffffffu, s, o);
    if (lane == 0) y[(size_t)b * sY + m] = s + (bias ? bias[m] : 0.f);
}

__global__ void matvec_uw_kernel(const float* __restrict__ Wq, const float* __restrict__ Wk,
                                 const float* __restrict__ hs,
                                 float* __restrict__ u, float* __restrict__ w)
{
    const float* W = blockIdx.z ? Wk : Wq;
    float* y = blockIdx.z ? w : u;
    int b = blockIdx.y;
    int m = (blockIdx.x << 3) + (threadIdx.x >> 5);
    int lane = threadIdx.x & 31;
    const float* wr = W + (size_t)m * CCH;
    const float* vv = hs + (size_t)b * CCH;
    float s = 0.f;
    for (int k = lane; k < CCH; k += 32) s += wr[k] * vv[k];
#pragma unroll
    for (int o = 16; o > 0; o >>= 1) s += __shfl_xor_sync(0xffffffffu, s, o);
    if (lane == 0) y[(size_t)b * CCH + m] = s;
}

// ---------------- launch ----------------
extern "C" void kernel_launch(void* const* d_in, const int* in_sizes, int n_in,
                              void* d_out, int out_size)
{
    const float* x     = (const float*)d_in[0];
    const float* gamma = (const float*)d_in[1];
    const float* beta  = (const float*)d_in[2];
    const float* Wq    = (const float*)d_in[3];
    const float* bq    = (const float*)d_in[4];
    const float* Wk    = (const float*)d_in[5];
    const float* bk    = (const float*)d_in[6];
    const float* Wv    = (const float*)d_in[7];
    const float* bv    = (const float*)d_in[8];
    const float* Wo    = (const float*)d_in[9];
    const float* bo    = (const float*)d_in[10];
    float* out = (float*)d_out;

    float *Gp, *G, *T1, *S, *attn, *T2, *P;
    float *ga, *be, *hs, *u, *w, *v1, *t, *r;
    cudaGetSymbolAddress((void**)&Gp,    g_Gp);
    cudaGetSymbolAddress((void**)&G,     g_G);
    cudaGetSymbolAddress((void**)&T1,    g_T1);
    cudaGetSymbolAddress((void**)&S,     g_S);
    cudaGetSymbolAddress((void**)&attn,  g_attn);
    cudaGetSymbolAddress((void**)&T2,    g_T2);
    cudaGetSymbolAddress((void**)&P,     g_P);
    cudaGetSymbolAddress((void**)&ga,    g_ga);
    cudaGetSymbolAddress((void**)&be,    g_be);
    cudaGetSymbolAddress((void**)&hs,    g_hs);
    cudaGetSymbolAddress((void**)&u,     g_u);
    cudaGetSymbolAddress((void**)&w,     g_w);
    cudaGetSymbolAddress((void**)&v1,    g_v1);
    cudaGetSymbolAddress((void**)&t,     g_t);
    cudaGetSymbolAddress((void**)&r,     g_r);

    cudaFuncSetAttribute((const void*)gemm_tc<false, false>, cudaFuncAttributeMaxDynamicSharedMemorySize, SMEM_PLAIN);
    cudaFuncSetAttribute((const void*)gemm_tc<false, true>,  cudaFuncAttributeMaxDynamicSharedMemorySize, SMEM_PLAIN);
    cudaFuncSetAttribute((const void*)gemm_tc<true, false>,  cudaFuncAttributeMaxDynamicSharedMemorySize, SMEM_SPLIT);

    const long long sF  = (long long)CCH * NPIX;
    const long long sAt = (long long)CCH * CCH;
    const long long sKsp = (long long)BATCH * CCH * CCH;
    const float scale = 1.0f / sqrtf((float)CCH);

    // 1) stats (ga/be/sx/hs), bias-correction vectors
    gn_stats_kernel<<<BATCH * 32, 256>>>(x, gamma, beta);
    matvec_uw_kernel<<<dim3(CCH / 8, BATCH, 2), 256>>>(Wq, Wk, hs, u, w);

    // 2) Gx = x x^T (raw Gram, NT), split-K; reduce + GN corrections; mirror
    gemm_tc<false, false><<<dim3(6, KSPLIT, BATCH), 256, SMEM_PLAIN>>>(
        x, NPIX, sF, x, NPIX, sF, Gp, CCH, sAt,
        nullptr, 0, 0, nullptr, nullptr, 1.f, NPIX / KSPLIT, 1, sKsp);
    reduce_g_kernel<<<dim3(256, BATCH), 256>>>(Gp, G);
    mirror_kernel<<<dim3(8, 8, BATCH), 256>>>(G);

    // 3) T1 = Wq G (NT, G symmetric); S = T1 Wk^T (NT)  — split-tf32 for score-path precision
    gemm_tc<true, false><<<dim3(4, 2, BATCH), 256, SMEM_SPLIT>>>(
        Wq, CCH, 0, G, CCH, sAt, T1, CCH, sAt, nullptr, 0, 0, nullptr, nullptr, 1.f, CCH, 0, 0);
    gemm_tc<true, false><<<dim3(4, 2, BATCH), 256, SMEM_SPLIT>>>(
        T1, CCH, sAt, Wk, CCH, 0, S, CCH, sAt, nullptr, 0, 0, nullptr, nullptr, 1.f, CCH, 0, 0);

    // 4) softmax (rank-1 bias corrections)
    softmax_kernel<<<(BATCH * CCH * 32) / 256, 256>>>(S, attn, u, w, bq, bk, scale);

    // 5) T2 = Wo attn (BNN: B=attn [K,N]); P' = (T2 Wv)(BNN: B=Wv [K,N]) * diag(ga)
    gemm_tc<false, true><<<dim3(4, 2, BATCH), 256, SMEM_PLAIN>>>(
        Wo, CCH, 0, attn, CCH, sAt, T2, CCH, sAt, nullptr, 0, 0, nullptr, nullptr, 1.f, CCH, 0, 0);
    gemm_tc<false, true><<<dim3(4, 2, BATCH), 256, SMEM_PLAIN>>>(
        T2, CCH, sAt, Wv, CCH, 0, P, CCH, sAt, nullptr, 0, 0, nullptr, ga, 1.f, CCH, 0, 0);

    // 6) r = Wo (attn (Wv be + bv)) + bo
    matvec_kernel<<<dim3(CCH / 8, BATCH), 256>>>(Wv, 0, be, CCH, nullptr, v1, CCH, nullptr);
    matvec_kernel<<<dim3(CCH / 8, BATCH), 256>>>(attn, sAt, v1, CCH, bv, t, CCH, nullptr);
    matvec_kernel<<<dim3(CCH / 8, BATCH), 256>>>(Wo, 0, t, CCH, nullptr, r, CCH, bo);

    // 7) out = P' x + r + x   (BNN: B = x [K=512 rows, N=4096 cols] directly — no transpose)
    gemm_tc<false, true><<<dim3(NPIX / 128, 2, BATCH), 256, SMEM_PLAIN>>>(
        P, CCH, sAt, x, NPIX, sF, out, NPIX, sF, r, 1, CCH, x, nullptr, 1.f, CCH, 0, 0);
}